// round 14
// baseline (speedup 1.0000x reference)
#include <cuda_runtime.h>
#include <math.h>

#define PH 11
#define PW 11
#define SCALEF 0.0625f
#define FH 200
#define FW 200
#define NC 256
#define CH_STRIDE (FH * FW)   // 40000 elements (160000 B, fits LDG imm offset)
#define CPW 4
#define WARPS 8

struct RowInfo { int off; float ly; };   // 8B -> single LDS.64

// Block = one roi x 32 channels; warp = 4 channels; lanes 0..21 = 22 x-samples
// (px = lane>>1, sx = lane&1; lanes >=22 mirror sample 21 -> broadcast loads).
// QUAD row cache: (A0,B0)..(A3,B3) = x-interp rows for the 4 sample rows of a
// 2-bin group. Reuse-chain branches depend only on smem row offsets (never on
// loaded data), so ALL load batches of the group issue back-to-back before the
// first consuming FMA -> one long-scoreboard stall per 2 bins (was 1/bin in
// the dual-cache version that measured 71.7us). Monotone reuse per step:
// equal -> copy; +FW -> shift B->A + load new B; else load both rows.
// Input ranges guarantee no boundary clamping.
__global__ __launch_bounds__(256) void roialign_maxpool_kernel(
    const float* __restrict__ feat,
    const float* __restrict__ rois,
    float* __restrict__ out)
{
    __shared__ RowInfo s_row[2 * PH + 2];   // +2 pad (never read)
    __shared__ float pooled[WARPS][CPW][PH][PW];

    const int k    = blockIdx.x;
    const int tid  = threadIdx.x;
    const int warp = tid >> 5;
    const int lane = tid & 31;
    const unsigned FULL = 0xffffffffu;

    const float x1 = __ldg(&rois[k * 5 + 1]) * SCALEF;
    const float y1 = __ldg(&rois[k * 5 + 2]) * SCALEF;
    const float x2 = __ldg(&rois[k * 5 + 3]) * SCALEF;
    const float y2 = __ldg(&rois[k * 5 + 4]) * SCALEF;
    const int   b  = (int)__ldg(&rois[k * 5 + 0]);

    const float bin_w = fmaxf(x2 - x1, 1.0f) * (1.0f / PW);
    const float bin_h = fmaxf(y2 - y1, 1.0f) * (1.0f / PH);

    // 22 y-sample rows once per block
    if (tid < 2 * PH) {
        float yc  = y1 + ((float)tid * 0.5f + 0.25f) * bin_h;
        int   ylo = (int)floorf(yc);
        s_row[tid].off = ylo * FW;
        s_row[tid].ly  = yc - (float)ylo;
    }

    // Per-lane x geometry
    const int  l  = min(lane, 2 * PW - 1);
    const int  px = l >> 1;
    const int  sx = l & 1;
    const bool store_lane = (lane < 2 * PW) && (sx == 0);

    float xc = x1 + ((float)px + 0.25f + 0.5f * (float)sx) * bin_w;
    const int   xlo = (int)floorf(xc);
    const float lx  = xc - (float)xlo;
    const float hx  = 1.0f - lx;

    const int c0 = blockIdx.y * (WARPS * CPW) + warp * CPW;
    const float* __restrict__ fbase =
        feat + ((size_t)(b * NC + c0)) * CH_STRIDE + xlo;

    __syncthreads();

#define LOADROW(DST, POFF)                                                     \
    {                                                                          \
        const float* __restrict__ _p = fbase + (POFF);                         \
        DST[0] = fmaf(lx, __ldg(_p + 0 * CH_STRIDE + 1), hx * __ldg(_p + 0 * CH_STRIDE)); \
        DST[1] = fmaf(lx, __ldg(_p + 1 * CH_STRIDE + 1), hx * __ldg(_p + 1 * CH_STRIDE)); \
        DST[2] = fmaf(lx, __ldg(_p + 2 * CH_STRIDE + 1), hx * __ldg(_p + 2 * CH_STRIDE)); \
        DST[3] = fmaf(lx, __ldg(_p + 3 * CH_STRIDE + 1), hx * __ldg(_p + 3 * CH_STRIDE)); \
    }
#define COPYROW(DST, SRC)                                                      \
    { DST[0] = SRC[0]; DST[1] = SRC[1]; DST[2] = SRC[2]; DST[3] = SRC[3]; }
    // (XA,XB) <- rows (OFF, OFF+FW), given (PA,PB) = rows (POFF, POFF+FW)
#define ESTABLISH(XA, XB, OFF, POFF, PA, PB)                                   \
    if ((OFF) == (POFF)) {                                                     \
        COPYROW(XA, PA) COPYROW(XB, PB)                                        \
    } else if ((OFF) == (POFF) + FW) {                                         \
        COPYROW(XA, PB) LOADROW(XB, (OFF) + FW)                                \
    } else {                                                                   \
        LOADROW(XA, (OFF)) LOADROW(XB, (OFF) + FW)                             \
    }

    // Persistent "previous last" cache
    float PA[CPW], PB[CPW];
    int   pOff = -0x40000000;

    // 5 groups of 2 bins (sample rows 0..19), then tail bin py=10 (rows 20,21)
    for (int py = 0; py < PH - 1; py += 2) {
        const RowInfo i0 = s_row[2 * py];
        const RowInfo i1 = s_row[2 * py + 1];
        const RowInfo i2 = s_row[2 * py + 2];
        const RowInfo i3 = s_row[2 * py + 3];

        float A0[CPW], B0[CPW], A1[CPW], B1[CPW];
        float A2[CPW], B2[CPW], A3[CPW], B3[CPW];

        ESTABLISH(A0, B0, i0.off, pOff,   PA, PB)
        ESTABLISH(A1, B1, i1.off, i0.off, A0, B0)
        ESTABLISH(A2, B2, i2.off, i1.off, A1, B1)
        ESTABLISH(A3, B3, i3.off, i2.off, A2, B2)
        pOff = i3.off;
        COPYROW(PA, A3) COPYROW(PB, B3)

        float a[CPW], c[CPW];
#pragma unroll
        for (int j = 0; j < CPW; ++j) {
            a[j] = fmaf(i0.ly, B0[j] - A0[j], A0[j])
                 + fmaf(i1.ly, B1[j] - A1[j], A1[j]);
            c[j] = fmaf(i2.ly, B2[j] - A2[j], A2[j])
                 + fmaf(i3.ly, B3[j] - A3[j], A3[j]);
        }
#pragma unroll
        for (int j = 0; j < CPW; ++j) {
            a[j] += __shfl_xor_sync(FULL, a[j], 1);
            c[j] += __shfl_xor_sync(FULL, c[j], 1);
        }
        if (store_lane) {
#pragma unroll
            for (int j = 0; j < CPW; ++j) {
                pooled[warp][j][py][px]     = a[j];
                pooled[warp][j][py + 1][px] = c[j];
            }
        }
    }

    // tail bin py = PH-1 (sample rows 20, 21)
    {
        const int py = PH - 1;
        const RowInfo i0 = s_row[2 * py];
        const RowInfo i1 = s_row[2 * py + 1];
        float A0[CPW], B0[CPW], A1[CPW], B1[CPW];
        ESTABLISH(A0, B0, i0.off, pOff,   PA, PB)
        ESTABLISH(A1, B1, i1.off, i0.off, A0, B0)

        float a[CPW];
#pragma unroll
        for (int j = 0; j < CPW; ++j)
            a[j] = fmaf(i0.ly, B0[j] - A0[j], A0[j])
                 + fmaf(i1.ly, B1[j] - A1[j], A1[j]);
#pragma unroll
        for (int j = 0; j < CPW; ++j)
            a[j] += __shfl_xor_sync(FULL, a[j], 1);
        if (store_lane) {
#pragma unroll
            for (int j = 0; j < CPW; ++j)
                pooled[warp][j][py][px] = a[j];
        }
    }
    __syncwarp();

    // 3x3 stride-2 maxpool over each 11x11 tile -> 5x5 (x0.25 folded here)
    if (lane < 25) {
        const int oy = lane / 5;
        const int ox = lane % 5;
#pragma unroll
        for (int j = 0; j < CPW; ++j) {
            float m = -INFINITY;
#pragma unroll
            for (int dy = 0; dy < 3; ++dy)
#pragma unroll
                for (int dx = 0; dx < 3; ++dx)
                    m = fmaxf(m, pooled[warp][j][2 * oy + dy][2 * ox + dx]);
            out[(((size_t)k * NC + (c0 + j)) * 5 + oy) * 5 + ox] = m * 0.25f;
        }
    }
}

extern "C" void kernel_launch(void* const* d_in, const int* in_sizes, int n_in,
                              void* d_out, int out_size)
{
    const float* feat = (const float*)d_in[0];
    const float* rois = (const float*)d_in[1];
    float* out = (float*)d_out;

    const int K = in_sizes[1] / 5;  // 512 rois

    dim3 grid(K, NC / (WARPS * CPW));   // (512, 8)
    dim3 block(256);
    roialign_maxpool_kernel<<<grid, block>>>(feat, rois, out);
}

// round 17
// speedup vs baseline: 1.0539x; 1.0539x over previous
#include <cuda_runtime.h>
#include <math.h>

#define PH 11
#define PW 11
#define SCALEF 0.0625f
#define FH 200
#define FW 200
#define NC 256
#define CH_STRIDE (FH * FW)   // 40000 elements (160000 B, fits LDG imm offset)
#define CPW 4
#define WARPS 8

// Per-bin descriptor, one LDS.128 per bin.
struct __align__(16) BinInfo {
    int   w;     // row offset (o0*FW) of the bin's first sample row
    int   sf;    // bits[0:3) = window shift s in {0..4}; bits[3:5) = d = o1-o0 in {0..2}
    float ly0;   // y-frac of sample row 0
    float ly1;   // y-frac of sample row 1
};

// Block = one roi x 32 channels; warp = 4 channels; lanes 0..21 = 22 x-samples
// (px=lane>>1, sx=lane&1; lanes>=22 mirror sample 21 -> broadcast loads).
// 4-ROW ROLLING WINDOW: R0..R3 = x-interp of rows (w .. w+3*FW).
// Intra-bin d = o1-o0 in {0,1,2} (sample gap bin_h/2 <= 1.42 -> floor diff
// up to 2; the 3-row version FAILED on d=2): A1=R[d], B1=R[d+1], d+1<=3.
// Inter-bin shift s = o0-o0_prev in {0..3} (bin gap <= 2.84); s=4 = bin 0.
// ONE warp-uniform branch chain per bin; per-bin load batches fused (one
// long-scoreboard stall/bin); d-select is branchless SEL. 16 cache regs =
// same budget as the 71.7us dual-cache kernel, half its branch regions.
// Bounds: o0 <= 193 -> w+3 <= 196 < 200; no clamping anywhere.
__global__ __launch_bounds__(256) void roialign_maxpool_kernel(
    const float* __restrict__ feat,
    const float* __restrict__ rois,
    float* __restrict__ out)
{
    __shared__ BinInfo s_bin[PH];
    __shared__ float pooled[WARPS][CPW][PH][PW];

    const int k    = blockIdx.x;
    const int tid  = threadIdx.x;
    const int warp = tid >> 5;
    const int lane = tid & 31;
    const unsigned FULL = 0xffffffffu;

    const float x1 = __ldg(&rois[k * 5 + 1]) * SCALEF;
    const float y1 = __ldg(&rois[k * 5 + 2]) * SCALEF;
    const float x2 = __ldg(&rois[k * 5 + 3]) * SCALEF;
    const float y2 = __ldg(&rois[k * 5 + 4]) * SCALEF;
    const int   b  = (int)__ldg(&rois[k * 5 + 0]);

    const float bin_w = fmaxf(x2 - x1, 1.0f) * (1.0f / PW);
    const float bin_h = fmaxf(y2 - y1, 1.0f) * (1.0f / PH);

    // Per-bin setup (threads 0..10)
    if (tid < PH) {
        float yc0 = y1 + ((float)tid + 0.25f) * bin_h;
        float yc1 = y1 + ((float)tid + 0.75f) * bin_h;
        int o0 = (int)floorf(yc0);
        int o1 = (int)floorf(yc1);
        int s;
        if (tid == 0) {
            s = 4;                                   // load all 4 rows
        } else {
            float ycp = y1 + ((float)tid - 0.75f) * bin_h;   // prev bin yc0
            s = o0 - (int)floorf(ycp);               // in {0,1,2,3}
        }
        int d = o1 - o0;                             // in {0,1,2}
        s_bin[tid].w   = o0 * FW;
        s_bin[tid].sf  = s | (d << 3);
        s_bin[tid].ly0 = yc0 - (float)o0;
        s_bin[tid].ly1 = yc1 - (float)o1;
    }

    // Per-lane x geometry
    const int  l  = min(lane, 2 * PW - 1);
    const int  px = l >> 1;
    const int  sx = l & 1;
    const bool store_lane = (lane < 2 * PW) && (sx == 0);

    float xc = x1 + ((float)px + 0.25f + 0.5f * (float)sx) * bin_w;
    const int   xlo = (int)floorf(xc);
    const float lx  = xc - (float)xlo;
    const float hx  = 1.0f - lx;

    const int c0 = blockIdx.y * (WARPS * CPW) + warp * CPW;
    const float* __restrict__ fbase =
        feat + ((size_t)(b * NC + c0)) * CH_STRIDE + xlo;

    __syncthreads();

#define LOADR(DST, POFF)                                                       \
    {                                                                          \
        const float* __restrict__ _p = fbase + (POFF);                         \
        DST[0] = fmaf(lx, __ldg(_p + 0 * CH_STRIDE + 1), hx * __ldg(_p + 0 * CH_STRIDE)); \
        DST[1] = fmaf(lx, __ldg(_p + 1 * CH_STRIDE + 1), hx * __ldg(_p + 1 * CH_STRIDE)); \
        DST[2] = fmaf(lx, __ldg(_p + 2 * CH_STRIDE + 1), hx * __ldg(_p + 2 * CH_STRIDE)); \
        DST[3] = fmaf(lx, __ldg(_p + 3 * CH_STRIDE + 1), hx * __ldg(_p + 3 * CH_STRIDE)); \
    }

    // Rolling window of x-interpolated rows (w, w+FW, w+2FW, w+3FW)
    float R0[CPW], R1[CPW], R2[CPW], R3[CPW];

    for (int py = 0; py < PH; ++py) {
        const BinInfo bi = s_bin[py];              // one LDS.128
        const int s = bi.sf & 7;
        const int d = bi.sf >> 3;
        const int w = bi.w;

        if (s) {                                   // warp-uniform chain
            if (s == 1) {
#pragma unroll
                for (int j = 0; j < CPW; ++j) { R0[j] = R1[j]; R1[j] = R2[j]; R2[j] = R3[j]; }
                LOADR(R3, w + 3 * FW)
            } else if (s == 2) {
#pragma unroll
                for (int j = 0; j < CPW; ++j) { R0[j] = R2[j]; R1[j] = R3[j]; }
                LOADR(R2, w + 2 * FW)
                LOADR(R3, w + 3 * FW)
            } else if (s == 3) {
#pragma unroll
                for (int j = 0; j < CPW; ++j) R0[j] = R3[j];
                LOADR(R1, w + FW)
                LOADR(R2, w + 2 * FW)
                LOADR(R3, w + 3 * FW)
            } else {                               // s == 4: all fresh
                LOADR(R0, w)
                LOADR(R1, w + FW)
                LOADR(R2, w + 2 * FW)
                LOADR(R3, w + 3 * FW)
            }
        }

        float a[CPW];
#pragma unroll
        for (int j = 0; j < CPW; ++j) {
            float v0 = fmaf(bi.ly0, R1[j] - R0[j], R0[j]);
            // branchless 3-way select on warp-uniform d
            float A1 = (d == 0) ? R0[j] : ((d == 1) ? R1[j] : R2[j]);
            float B1 = (d == 0) ? R1[j] : ((d == 1) ? R2[j] : R3[j]);
            float v1 = fmaf(bi.ly1, B1 - A1, A1);
            a[j] = v0 + v1;
        }

        // fold sx pair; even lanes hold the bin sum (x0.25 folded in epilogue)
#pragma unroll
        for (int j = 0; j < CPW; ++j)
            a[j] += __shfl_xor_sync(FULL, a[j], 1);
        if (store_lane) {
#pragma unroll
            for (int j = 0; j < CPW; ++j)
                pooled[warp][j][py][px] = a[j];
        }
    }
    __syncwarp();

    // 3x3 stride-2 maxpool over each 11x11 tile -> 5x5 (x0.25 folded here)
    if (lane < 25) {
        const int oy = lane / 5;
        const int ox = lane % 5;
#pragma unroll
        for (int j = 0; j < CPW; ++j) {
            float m = -INFINITY;
#pragma unroll
            for (int dy = 0; dy < 3; ++dy)
#pragma unroll
                for (int dx = 0; dx < 3; ++dx)
                    m = fmaxf(m, pooled[warp][j][2 * oy + dy][2 * ox + dx]);
            out[(((size_t)k * NC + (c0 + j)) * 5 + oy) * 5 + ox] = m * 0.25f;
        }
    }
}

extern "C" void kernel_launch(void* const* d_in, const int* in_sizes, int n_in,
                              void* d_out, int out_size)
{
    const float* feat = (const float*)d_in[0];
    const float* rois = (const float*)d_in[1];
    float* out = (float*)d_out;

    const int K = in_sizes[1] / 5;  // 512 rois

    dim3 grid(K, NC / (WARPS * CPW));   // (512, 8)
    dim3 block(256);
    roialign_maxpool_kernel<<<grid, block>>>(feat, rois, out);
}